// round 2
// baseline (speedup 1.0000x reference)
#include <cuda_runtime.h>

#define B_   32
#define CI   256
#define COUT 256
#define Hs   56
#define Ws   56
#define HW   3136
#define NPOS 100352      // B_*HW
#define TOT  25690112    // B_*COUT*HW

#define TH 8
#define TW 8

// ---------------- device scratch (static: no runtime allocation) ----------------
__device__ unsigned long long g_A[NPOS * 4];        // packed activations [pos][4]
__device__ unsigned long long g_W[COUT * 36];       // packed weights [co][tap*4+seg]
__device__ float              g_alpha[COUT];
__device__ int                g_sumS[COUT];
__device__ unsigned long long g_sumSq[COUT];
__device__ short              g_S[TOT];             // conv integer result
__device__ int                g_ti[COUT];
__device__ int                g_mode[COUT];

// ---------------- kernel 0: zero stats ----------------
__global__ void k_zero() {
    int t = threadIdx.x;
    g_sumS[t] = 0;
    g_sumSq[t] = 0ULL;
}

// ---------------- kernel 1: binarize + bit-pack activations ----------------
// grid (784, 4), block 128. Each thread packs 64 channels for one pixel.
__global__ void k_pack(const float* __restrict__ x) {
    int p   = blockIdx.x * 128 + threadIdx.x;   // 0..NPOS-1 (784*128 == NPOS)
    int seg = blockIdx.y;                       // 0..3
    int b  = p / HW;
    int hw = p - b * HW;
    const float* xp = x + ((size_t)b * CI + (size_t)seg * 64) * HW + hw;
    unsigned long long bits = 0ULL;
#pragma unroll
    for (int i = 0; i < 64; i++) {
        float v = xp[(size_t)i * HW];
        bits |= (unsigned long long)(v > 0.0f) << i;
    }
    g_A[(size_t)p * 4 + seg] = bits;
}

// ---------------- kernel 2: weight prep (mean-center, alpha, pack signs) ------
// one block per co, 256 threads (= ci)
__global__ void k_wprep(const float* __restrict__ wgt) {
    int co   = blockIdx.x;
    int ci   = threadIdx.x;
    int lane = ci & 31, warp = ci >> 5;

    __shared__ double smp[8][9];
    __shared__ double smean[9];
    __shared__ unsigned int sbits[9 * 8];
    __shared__ float sal[8];

    float wv[9];
    const float* wp = wgt + ((size_t)co * CI + ci) * 9;
#pragma unroll
    for (int k = 0; k < 9; k++) wv[k] = wp[k];

    // per-tap mean over ci, reduced in double (sign-flip safety vs reference)
#pragma unroll
    for (int k = 0; k < 9; k++) {
        double v = (double)wv[k];
        for (int o = 16; o; o >>= 1) v += __shfl_xor_sync(0xffffffffu, v, o);
        if (lane == 0) smp[warp][k] = v;
    }
    __syncthreads();
    if (ci < 9) {
        double s = 0.0;
        for (int w = 0; w < 8; w++) s += smp[w][ci];
        smean[ci] = s * (1.0 / 256.0);
    }
    __syncthreads();

    float asum = 0.0f;
#pragma unroll
    for (int k = 0; k < 9; k++) {
        double wcd = (double)wv[k] - smean[k];
        float wc = (float)wcd;
        wc = fminf(fmaxf(wc, -1.0f), 1.0f);
        asum += fabsf(wc);
        unsigned m = __ballot_sync(0xffffffffu, wcd > 0.0);
        if (lane == 0) sbits[k * 8 + warp] = m;
    }
    for (int o = 16; o; o >>= 1) asum += __shfl_xor_sync(0xffffffffu, asum, o);
    if (lane == 0) sal[warp] = asum;
    __syncthreads();

    if (ci == 0) {
        float t = 0.0f;
        for (int w = 0; w < 8; w++) t += sal[w];
        g_alpha[co] = t * (1.0f / 2304.0f);
    }
    if (ci < 36) {
        int k = ci >> 2, j = ci & 3;
        unsigned lo = sbits[k * 8 + 2 * j];
        unsigned hi = sbits[k * 8 + 2 * j + 1];
        g_W[(size_t)co * 36 + k * 4 + j] =
            (unsigned long long)lo | ((unsigned long long)hi << 32);
    }
}

// ---------------- kernel 3: XNOR-popcount conv + channel stats ----------------
// grid (7,7,32), block 256 (= co). Tile 8x8 outputs, 10x10 halo in smem.
__global__ void __launch_bounds__(256) k_conv() {
    __shared__ unsigned long long sA[(TH + 2) * (TW + 2) * 4];
    int b  = blockIdx.z;
    int h0 = blockIdx.y * TH;
    int w0 = blockIdx.x * TW;
    int co = threadIdx.x;

    // load 10x10 halo of packed activations (zero out-of-range)
    for (int idx = threadIdx.x; idx < (TH + 2) * (TW + 2) * 4; idx += 256) {
        int seg = idx & 3;
        int pos = idx >> 2;
        int i = pos / (TW + 2), j = pos - i * (TW + 2);
        int hh = h0 - 1 + i, ww = w0 - 1 + j;
        unsigned long long v = 0ULL;
        if ((unsigned)hh < Hs && (unsigned)ww < Ws)
            v = g_A[((size_t)(b * HW + hh * Ws + ww)) * 4 + seg];
        sA[idx] = v;
    }

    // per-thread weights in registers (36 x u64)
    unsigned long long wr[36];
#pragma unroll
    for (int t = 0; t < 36; t++) wr[t] = g_W[(size_t)co * 36 + t];
    __syncthreads();

    int tsum = 0;
    long long tsq = 0;
    short* outp = &g_S[((size_t)(b * COUT + co)) * HW];

    for (int py = 0; py < TH; py++) {
        int h = h0 + py;
#pragma unroll
        for (int px = 0; px < TW; px++) {
            int w = w0 + px;
            int s = 0;
#pragma unroll
            for (int kh = 0; kh < 3; kh++) {
                int hh = h + kh - 1;
                bool vr = (unsigned)hh < Hs;
#pragma unroll
                for (int kw = 0; kw < 3; kw++) {
                    int ww = w + kw - 1;
                    bool v = vr && ((unsigned)ww < Ws);
                    const ulonglong2* ap = reinterpret_cast<const ulonglong2*>(
                        &sA[((py + kh) * (TW + 2) + (px + kw)) * 4]);
                    ulonglong2 a0 = ap[0];
                    ulonglong2 a1 = ap[1];
                    int k = (kh * 3 + kw) * 4;
                    int m = __popcll(a0.x ^ wr[k + 0]) + __popcll(a0.y ^ wr[k + 1]) +
                            __popcll(a1.x ^ wr[k + 2]) + __popcll(a1.y ^ wr[k + 3]);
                    s += v ? (256 - 2 * m) : 0;
                }
            }
            outp[h * Ws + w] = (short)s;
            tsum += s;
            tsq  += (long long)(s * s);
        }
    }
    atomicAdd(&g_sumS[co], tsum);
    atomicAdd(&g_sumSq[co], (unsigned long long)tsq);
}

// ---------------- kernel 4: per-channel integer threshold ----------------
__global__ void k_thresh(const float* __restrict__ gamma,
                         const float* __restrict__ beta) {
    int co = threadIdx.x;
    double M      = (double)NPOS;
    double mean_s = (double)g_sumS[co] / M;
    double var_s  = (double)g_sumSq[co] / M - mean_s * mean_s;
    double al     = (double)g_alpha[co];
    double inv    = 1.0 / sqrt(al * al * var_s + 1e-5);
    double scale  = (double)gamma[co] * al * inv;
    double be     = (double)beta[co];

    int mode;
    int ti = 0;
    if (scale > 0.0) {
        mode = 1;
        double t = mean_s - be / scale;     // output 1 iff s > t  -> s >= floor(t)+1
        t = fmin(fmax(t, -1.0e7), 1.0e7);
        ti = (int)floor(t) + 1;
    } else if (scale < 0.0) {
        mode = -1;
        double t = mean_s - be / scale;     // output 1 iff s < t  -> s <= ceil(t)-1
        t = fmin(fmax(t, -1.0e7), 1.0e7);
        ti = (int)ceil(t) - 1;
    } else {
        mode = (be > 0.0) ? 2 : 0;
    }
    g_ti[co]   = ti;
    g_mode[co] = mode;
}

// ---------------- kernel 5: threshold map -> float {0,1} ----------------
__global__ void k_pass2(float* __restrict__ out) {
    int i    = blockIdx.x * blockDim.x + threadIdx.x;
    int base = i * 4;                       // TOT % 4 == 0, grid covers exactly
    int co   = (base / HW) & 255;
    int ti   = g_ti[co];
    int mode = g_mode[co];
    short4 s = *reinterpret_cast<const short4*>(&g_S[base]);
    float4 o;
    if (mode == 1) {
        o.x = (s.x >= ti) ? 1.0f : 0.0f;
        o.y = (s.y >= ti) ? 1.0f : 0.0f;
        o.z = (s.z >= ti) ? 1.0f : 0.0f;
        o.w = (s.w >= ti) ? 1.0f : 0.0f;
    } else if (mode == -1) {
        o.x = (s.x <= ti) ? 1.0f : 0.0f;
        o.y = (s.y <= ti) ? 1.0f : 0.0f;
        o.z = (s.z <= ti) ? 1.0f : 0.0f;
        o.w = (s.w <= ti) ? 1.0f : 0.0f;
    } else {
        float c = (mode == 2) ? 1.0f : 0.0f;
        o.x = c; o.y = c; o.z = c; o.w = c;
    }
    *reinterpret_cast<float4*>(&out[base]) = o;
}

// ---------------- launch ----------------
extern "C" void kernel_launch(void* const* d_in, const int* in_sizes, int n_in,
                              void* d_out, int out_size) {
    const float* x     = (const float*)d_in[0];
    const float* wgt   = (const float*)d_in[1];
    // d_in[2] = bias: cancels analytically (y-mu), not needed
    const float* gamma = (const float*)d_in[3];
    const float* beta  = (const float*)d_in[4];
    float* out = (float*)d_out;

    k_zero  <<<1, 256>>>();
    k_pack  <<<dim3(784, 4), 128>>>(x);
    k_wprep <<<256, 256>>>(wgt);
    k_conv  <<<dim3(7, 7, 32), 256>>>();
    k_thresh<<<1, 256>>>(gamma, beta);
    k_pass2 <<<TOT / 4 / 256, 256>>>(out);
}